// round 12
// baseline (speedup 1.0000x reference)
#include <cuda_runtime.h>
#include <cstdint>

// ---------------------------------------------------------------------------
// ClockworkGRU:
//   Phase A: clockwork-sparse projections (47% of dense GEMM).
//   Phase B: scan — 4-CTA cluster per PAIR of batch rows (R10 structure).
//   v12: block 0 (active EVERY step) is computed fully redundantly by every
//        rank from a complete SMEM copy of its matrices -> odd steps need no
//        cluster barriers or DSMEM exchange at all. Blocks 1-3 streamed with
//        warp-coalesced dots (block 1 no longer SMEM-cached).
// ---------------------------------------------------------------------------

#define GM 32768
#define GK 512
#define GN 512
#define SEQ_LEN 512
#define NBATCH 64

__device__ float g_proj[3ull * GM * GN];

// streamed blocks 1..3: seg counts and partial-buffer bases
__constant__ int c_SRn[4]  = {0, 4, 6, 8};      // r/z/h segs (64-deep)
__constant__ int c_RPBn[4] = {0, 0, 512, 1664}; // r partial bases (in rp)
__constant__ int c_ZPBn[4] = {0, 0, 256, 640};  // z / hn partial bases
__constant__ int c_OFF[4]  = {0, 128, 384, 768};

// ---------------- helpers ----------------------------------------------------
__device__ __forceinline__ unsigned long long pack2(float x, float y) {
    unsigned long long r;
    asm("mov.b64 %0, {%1, %2};" : "=l"(r) : "f"(x), "f"(y));
    return r;
}
__device__ __forceinline__ void fma2(unsigned long long& d,
                                     unsigned long long a,
                                     unsigned long long b) {
    asm("fma.rn.f32x2 %0, %1, %2, %0;" : "+l"(d) : "l"(a), "l"(b));
}
__device__ __forceinline__ float2 unpack2(unsigned long long v) {
    float2 r;
    asm("mov.b64 {%0, %1}, %2;" : "=f"(r.x), "=f"(r.y) : "l"(v));
    return r;
}
__device__ __forceinline__ float sigmoidf_(float x) {
    return 1.0f / (1.0f + __expf(-x));
}
__device__ __forceinline__ uint32_t smem_u32(const void* p) {
    return (uint32_t)__cvta_generic_to_shared(p);
}
__device__ __forceinline__ uint32_t mapa_u32(uint32_t addr, uint32_t rank) {
    uint32_t r;
    asm("mapa.shared::cluster.u32 %0, %1, %2;" : "=r"(r) : "r"(addr), "r"(rank));
    return r;
}
__device__ __forceinline__ void st_cluster_b64(uint32_t a, float x, float y) {
    unsigned long long v = pack2(x, y);
    asm volatile("st.shared::cluster.b64 [%0], %1;" :: "r"(a), "l"(v) : "memory");
}
#define CLUSTER_SYNC() do {                                           \
    asm volatile("barrier.cluster.arrive.aligned;" ::: "memory");     \
    asm volatile("barrier.cluster.wait.aligned;"   ::: "memory");     \
} while (0)

// ---------------------------------------------------------------------------
// Clockwork-sparse GEMM (unchanged — measured ~0.43 ms)
// ---------------------------------------------------------------------------
#define BM 128
#define BN 128
#define BKK 8

__global__ void __launch_bounds__(256) gemm3_kernel(
    const float* __restrict__ A,
    const float* __restrict__ W0, const float* __restrict__ b0,
    const float* __restrict__ W1, const float* __restrict__ b1,
    const float* __restrict__ W2, const float* __restrict__ b2)
{
    __shared__ float As[BKK][BM];
    __shared__ float Bs[BKK][BN];

    const int zi = blockIdx.z;
    const int z  = zi >> 2;
    const int cb = zi & 3;
    const int rpb_log = 9 - cb;
    const int ntiles = (NBATCH << rpb_log) >> 7;
    if ((int)blockIdx.y >= ntiles) return;

    const float* W    = (z == 0) ? W0 : (z == 1 ? W1 : W2);
    const float* bias = (z == 0) ? b0 : (z == 1 ? b1 : b2);
    float* C = g_proj + (size_t)z * GM * GN;

    const int m0 = blockIdx.y * BM;
    const int n0 = cb * 128;
    const int tid = threadIdx.x;

    const int a_row = tid >> 1;
    const int a_k   = (tid & 1) * 4;
    const int b_row = tid >> 5;
    const int b_col = (tid & 31) * 4;

    const int warp = tid >> 5;
    const int lane = tid & 31;
    const int row0 = (warp & 3) * 32 + (lane & 3) * 8;
    const int col0 = (warp >> 2) * 64 + (lane >> 2) * 8;

    const int rpb_mask = (1 << rpb_log) - 1;
    const int gA = m0 + a_row;
    const int arow_act = ((gA >> rpb_log) << 9) + ((gA & rpb_mask) << cb);

    unsigned long long acc[8][4];
#pragma unroll
    for (int i = 0; i < 8; i++)
#pragma unroll
        for (int j = 0; j < 4; j++) acc[i][j] = 0ull;

    const float* Aptr = A + (size_t)arow_act * GK + a_k;
    const float* Wptr = W + (size_t)b_row * GN + n0 + b_col;

    float4 ra = *(const float4*)Aptr;
    float4 rb = *(const float4*)Wptr;

    const int KT = GK / BKK;
    for (int kt = 0; kt < KT; kt++) {
        As[a_k + 0][a_row] = ra.x;
        As[a_k + 1][a_row] = ra.y;
        As[a_k + 2][a_row] = ra.z;
        As[a_k + 3][a_row] = ra.w;
        *(float4*)&Bs[b_row][b_col] = rb;
        __syncthreads();

        if (kt + 1 < KT) {
            ra = *(const float4*)(Aptr + (kt + 1) * BKK);
            rb = *(const float4*)(Wptr + (size_t)(kt + 1) * BKK * GN);
        }

#pragma unroll
        for (int k = 0; k < BKK; k++) {
            float4 a0 = *(const float4*)&As[k][row0];
            float4 a1 = *(const float4*)&As[k][row0 + 4];
            ulonglong2 bq0 = *(const ulonglong2*)&Bs[k][col0];
            ulonglong2 bq1 = *(const ulonglong2*)&Bs[k][col0 + 4];
            unsigned long long av[8];
            av[0] = pack2(a0.x, a0.x); av[1] = pack2(a0.y, a0.y);
            av[2] = pack2(a0.z, a0.z); av[3] = pack2(a0.w, a0.w);
            av[4] = pack2(a1.x, a1.x); av[5] = pack2(a1.y, a1.y);
            av[6] = pack2(a1.z, a1.z); av[7] = pack2(a1.w, a1.w);
#pragma unroll
            for (int i = 0; i < 8; i++) {
                fma2(acc[i][0], av[i], bq0.x);
                fma2(acc[i][1], av[i], bq0.y);
                fma2(acc[i][2], av[i], bq1.x);
                fma2(acc[i][3], av[i], bq1.y);
            }
        }
        __syncthreads();
    }

    float bb[8];
#pragma unroll
    for (int j = 0; j < 8; j++) bb[j] = bias[n0 + col0 + j];

#pragma unroll
    for (int i = 0; i < 8; i++) {
        float o[8];
#pragma unroll
        for (int jp = 0; jp < 4; jp++) {
            float2 v = unpack2(acc[i][jp]);
            o[2 * jp]     = v.x + bb[2 * jp];
            o[2 * jp + 1] = v.y + bb[2 * jp + 1];
        }
        const int g2 = m0 + row0 + i;
        const int crow = ((g2 >> rpb_log) << 9) + ((g2 & rpb_mask) << cb);
        size_t base = (size_t)crow * GN + n0 + col0;
        *(float4*)&C[base]     = make_float4(o[0], o[1], o[2], o[3]);
        *(float4*)&C[base + 4] = make_float4(o[4], o[5], o[6], o[7]);
    }
}

// ---------------------------------------------------------------------------
// warp-coalesced 2-row dots over 64 k-rows
// ---------------------------------------------------------------------------

template<int WIDE>  // 32 (128 cols) or 24 (96 cols); lanes < WIDE active
__device__ __forceinline__ void wdot_wide2(const float* __restrict__ Wp, int stride,
                                           const float* __restrict__ h0,
                                           const float* __restrict__ h1,
                                           float* a0, float* a1, int lane)
{
    const float* p = Wp + lane * 4;
    float4 A[8], B[8];
#pragma unroll
    for (int r = 0; r < 8; r++) A[r] = *(const float4*)(p + (size_t)r * stride);
#pragma unroll
    for (int kb = 0; kb < 64; kb += 16) {
#pragma unroll
        for (int r = 0; r < 8; r++)
            B[r] = *(const float4*)(p + (size_t)(kb + 8 + r) * stride);
#pragma unroll
        for (int r = 0; r < 8; r++) {
            float x0 = h0[kb + r], x1 = h1[kb + r];
            a0[0] = fmaf(x0, A[r].x, a0[0]); a0[1] = fmaf(x0, A[r].y, a0[1]);
            a0[2] = fmaf(x0, A[r].z, a0[2]); a0[3] = fmaf(x0, A[r].w, a0[3]);
            a1[0] = fmaf(x1, A[r].x, a1[0]); a1[1] = fmaf(x1, A[r].y, a1[1]);
            a1[2] = fmaf(x1, A[r].z, a1[2]); a1[3] = fmaf(x1, A[r].w, a1[3]);
        }
        if (kb + 16 < 64) {
#pragma unroll
            for (int r = 0; r < 8; r++)
                A[r] = *(const float4*)(p + (size_t)(kb + 16 + r) * stride);
        }
#pragma unroll
        for (int r = 0; r < 8; r++) {
            float x0 = h0[kb + 8 + r], x1 = h1[kb + 8 + r];
            a0[0] = fmaf(x0, B[r].x, a0[0]); a0[1] = fmaf(x0, B[r].y, a0[1]);
            a0[2] = fmaf(x0, B[r].z, a0[2]); a0[3] = fmaf(x0, B[r].w, a0[3]);
            a1[0] = fmaf(x1, B[r].x, a1[0]); a1[1] = fmaf(x1, B[r].y, a1[1]);
            a1[2] = fmaf(x1, B[r].z, a1[2]); a1[3] = fmaf(x1, B[r].w, a1[3]);
        }
    }
}

// 32-col window, arbitrary row stride: 4 rows x 8 col-quads per warp-load,
// 64 rows; all loads prefetched; shfl reduce; lanes 0-7 hold column sums.
__device__ __forceinline__ void wdot_w8s2(const float* __restrict__ Wp, int stride,
                                          const float* __restrict__ h0,
                                          const float* __restrict__ h1,
                                          float* a0, float* a1, int lane)
{
    const int sr = lane >> 3, sc = lane & 7;
    const float* p = Wp + sr * stride + sc * 4;
    float4 A[8], B[8];
#pragma unroll
    for (int i = 0; i < 8; i++)
        A[i] = *(const float4*)(p + (size_t)(i * 4) * stride);
#pragma unroll
    for (int i = 0; i < 8; i++)
        B[i] = *(const float4*)(p + (size_t)((i + 8) * 4) * stride);
#pragma unroll
    for (int i = 0; i < 8; i++) {
        float x0 = h0[i * 4 + sr], x1 = h1[i * 4 + sr];
        a0[0] = fmaf(x0, A[i].x, a0[0]); a0[1] = fmaf(x0, A[i].y, a0[1]);
        a0[2] = fmaf(x0, A[i].z, a0[2]); a0[3] = fmaf(x0, A[i].w, a0[3]);
        a1[0] = fmaf(x1, A[i].x, a1[0]); a1[1] = fmaf(x1, A[i].y, a1[1]);
        a1[2] = fmaf(x1, A[i].z, a1[2]); a1[3] = fmaf(x1, A[i].w, a1[3]);
    }
#pragma unroll
    for (int i = 0; i < 8; i++) {
        float x0 = h0[(i + 8) * 4 + sr], x1 = h1[(i + 8) * 4 + sr];
        a0[0] = fmaf(x0, B[i].x, a0[0]); a0[1] = fmaf(x0, B[i].y, a0[1]);
        a0[2] = fmaf(x0, B[i].z, a0[2]); a0[3] = fmaf(x0, B[i].w, a0[3]);
        a1[0] = fmaf(x1, B[i].x, a1[0]); a1[1] = fmaf(x1, B[i].y, a1[1]);
        a1[2] = fmaf(x1, B[i].z, a1[2]); a1[3] = fmaf(x1, B[i].w, a1[3]);
    }
#pragma unroll
    for (int j = 0; j < 4; j++) {
        a0[j] += __shfl_xor_sync(0xffffffffu, a0[j], 8);
        a0[j] += __shfl_xor_sync(0xffffffffu, a0[j], 16);
        a1[j] += __shfl_xor_sync(0xffffffffu, a1[j], 8);
        a1[j] += __shfl_xor_sync(0xffffffffu, a1[j], 16);
    }
}

__device__ __forceinline__ void fold4(float* a, const float4& b) {
    a[0] += b.x; a[1] += b.y; a[2] += b.z; a[3] += b.w;
}

// ---------------------------------------------------------------------------
__global__ void __launch_bounds__(512, 1) __cluster_dims__(4, 1, 1)
scan_kernel(
    const float* __restrict__ ch0, const float* __restrict__ cr0, const float* __restrict__ cz0,
    const float* __restrict__ ch1, const float* __restrict__ cr1, const float* __restrict__ cz1,
    const float* __restrict__ ch2, const float* __restrict__ cr2, const float* __restrict__ cz2,
    const float* __restrict__ ch3, const float* __restrict__ cr3, const float* __restrict__ cz3,
    float* __restrict__ out)
{
    extern __shared__ float smem[];
    float* h_s   = smem;              // 2 x 512
    float* rh_s  = smem + 1024;       // 2 x 1280
    float* zb0   = smem + 3584;       // 2 x 128 (sigmoided block0 z)
    float* rp    = smem + 3840;       // 3712 r partials (b1..b3)
    float* zp    = smem + 7552;       // 1152 z partials (b1..b3)
    float* hp    = rp;                // hn partials alias rp (disjoint in time)
    float* cr0_s = smem + 8704;       // 128 x 128 FULL
    float* cz0_s = smem + 25088;      // 128 x 128 FULL
    float* ch0_s = smem + 41472;      // 128 x 128 FULL (end 57856 fl = 231,424 B)

    const int rank = blockIdx.x & 3;
    const int bp   = blockIdx.x >> 2;
    const int tid  = threadIdx.x;
    const int wid  = tid >> 5;
    const int lane = tid & 31;

    // preload FULL block-0 matrices (192 KB)
    {
        const float4* s1 = (const float4*)cr0; float4* d1 = (float4*)cr0_s;
        const float4* s2 = (const float4*)cz0; float4* d2 = (float4*)cz0_s;
        const float4* s3 = (const float4*)ch0; float4* d3 = (float4*)ch0_s;
        for (int i = tid; i < 4096; i += 512) {
            d1[i] = s1[i]; d2[i] = s2[i]; d3[i] = s3[i];
        }
    }
    h_s[tid] = 0.0f; h_s[512 + tid] = 0.0f;
    __syncthreads();
    CLUSTER_SYNC();

    uint32_t peer_rh[3], peer_h[3];
    {
        int p = 0;
        for (int r = 0; r < 4; r++) {
            if (r == rank) continue;
            peer_rh[p] = mapa_u32(smem_u32(rh_s), (uint32_t)r);
            peer_h[p]  = mapa_u32(smem_u32(h_s),  (uint32_t)r);
            p++;
        }
    }

    const float* xt  = g_proj;
    const float* xrt = g_proj + (size_t)GM * GN;
    const float* xzt = g_proj + 2ull * GM * GN;

    for (int t = 0; t < SEQ_LEN; t++) {
        const bool aa1 = (t & 1) == 0, aa2 = (t & 3) == 0, aa3 = (t & 7) == 0;
        int sact[3]; int ns = 0;                 // streamed active blocks
        if (aa1) sact[ns++] = 1;
        if (aa2) sact[ns++] = 2;
        if (aa3) sact[ns++] = 3;

        const size_t xr0 = ((size_t)(bp * 2 + 0) * SEQ_LEN + t) * GN;
        const size_t xr1 = ((size_t)(bp * 2 + 1) * SEQ_LEN + t) * GN;

        // ============ pass 1 ================================================
        // (a) warp tasks: streamed blocks 1-3 r/z dots -> private partials
        {
            const int nwt = (aa1 ? 12 : 0) + (aa2 ? 12 : 0) + (aa3 ? 16 : 0);
            for (int wt = wid; wt < nwt; wt += 16) {
                int k = wt;
                float A0[4] = {0,0,0,0}, A1[4] = {0,0,0,0};
                if (aa1) {
                    if (k < 8) {                      // b1 r: 2 groups x 4 segs
                        const int seg = k >> 1, g = k & 1;
                        wdot_w8s2(cr1 + (size_t)(seg * 64) * 256
                                      + rank * 64 + g * 32, 256,
                                  h_s + seg * 64, h_s + 512 + seg * 64,
                                  A0, A1, lane);
                        if (lane < 8) {
                            const int c = g * 32 + lane * 4;
                            if (seg == 0) {
                                fold4(A0, *(const float4*)&xrt[xr0 + rank * 64 + c]);
                                fold4(A1, *(const float4*)&xrt[xr1 + rank * 64 + c]);
                            }
                            float* P = rp + seg * 128 + c;
                            *(float4*)P        = make_float4(A0[0],A0[1],A0[2],A0[3]);
                            *(float4*)(P + 64) = make_float4(A1[0],A1[1],A1[2],A1[3]);
                        }
                        continue;
                    }
                    k -= 8;
                    if (k < 4) {                      // b1 z: 4 segs
                        const int seg = k;
                        wdot_w8s2(cz1 + (size_t)(seg * 64) * 128 + rank * 32, 128,
                                  h_s + seg * 64, h_s + 512 + seg * 64,
                                  A0, A1, lane);
                        if (lane < 8) {
                            const int c = lane * 4;
                            if (seg == 0) {
                                fold4(A0, *(const float4*)&xzt[xr0 + 128 + rank * 32 + c]);
                                fold4(A1, *(const float4*)&xzt[xr1 + 128 + rank * 32 + c]);
                            }
                            float* P = zp + seg * 64 + c;
                            *(float4*)P        = make_float4(A0[0],A0[1],A0[2],A0[3]);
                            *(float4*)(P + 32) = make_float4(A1[0],A1[1],A1[2],A1[3]);
                        }
                        continue;
                    }
                    k -= 4;
                }
                if (aa2) {
                    if (k < 6) {                      // b2 r
                        const int seg = k;
                        if (lane < 24) {
                            wdot_wide2<24>(cr2 + (size_t)(seg * 64) * 384 + rank * 96,
                                           384, h_s + seg * 64, h_s + 512 + seg * 64,
                                           A0, A1, lane);
                            const int c = lane * 4;
                            if (seg == 0) {
                                fold4(A0, *(const float4*)&xrt[xr0 + rank * 96 + c]);
                                fold4(A1, *(const float4*)&xrt[xr1 + rank * 96 + c]);
                            }
                            float* P = rp + 512 + seg * 192 + c;
                            *(float4*)P        = make_float4(A0[0],A0[1],A0[2],A0[3]);
                            *(float4*)(P + 96) = make_float4(A1[0],A1[1],A1[2],A1[3]);
                        }
                        continue;
                    }
                    k -= 6;
                    if (k < 6) {                      // b2 z
                        const int seg = k;
                        wdot_w8s2(cz2 + (size_t)(seg * 64) * 128 + rank * 32, 128,
                                  h_s + seg * 64, h_s + 512 + seg * 64,
                                  A0, A1, lane);
                        if (lane < 8) {
                            const int c = lane * 4;
                            if (seg == 0) {
                                fold4(A0, *(const float4*)&xzt[xr0 + 256 + rank * 32 + c]);
                                fold4(A1, *(const float4*)&xzt[xr1 + 256 + rank * 32 + c]);
                            }
                            float* P = zp + 256 + seg * 64 + c;
                            *(float4*)P        = make_float4(A0[0],A0[1],A0[2],A0[3]);
                            *(float4*)(P + 32) = make_float4(A1[0],A1[1],A1[2],A1[3]);
                        }
                        continue;
                    }
                    k -= 6;
                }
                if (k < 8) {                          // b3 r
                    const int seg = k;
                    wdot_wide2<32>(cr3 + (size_t)(seg * 64) * 512 + rank * 128,
                                   512, h_s + seg * 64, h_s + 512 + seg * 64,
                                   A0, A1, lane);
                    const int c = lane * 4;
                    if (seg == 0) {
                        fold4(A0, *(const float4*)&xrt[xr0 + rank * 128 + c]);
                        fold4(A1, *(const float4*)&xrt[xr1 + rank * 128 + c]);
                    }
                    float* P = rp + 1664 + seg * 256 + c;
                    *(float4*)P         = make_float4(A0[0],A0[1],A0[2],A0[3]);
                    *(float4*)(P + 128) = make_float4(A1[0],A1[1],A1[2],A1[3]);
                } else {                              // b3 z
                    const int seg = k - 8;
                    wdot_w8s2(cz3 + (size_t)(seg * 64) * 128 + rank * 32, 128,
                              h_s + seg * 64, h_s + 512 + seg * 64, A0, A1, lane);
                    if (lane < 8) {
                        const int c = lane * 4;
                        if (seg == 0) {
                            fold4(A0, *(const float4*)&xzt[xr0 + 384 + rank * 32 + c]);
                            fold4(A1, *(const float4*)&xzt[xr1 + 384 + rank * 32 + c]);
                        }
                        float* P = zp + 640 + seg * 64 + c;
                        *(float4*)P        = make_float4(A0[0],A0[1],A0[2],A0[3]);
                        *(float4*)(P + 32) = make_float4(A1[0],A1[1],A1[2],A1[3]);
                    }
                }
            }
        }
        // (b) block0 (redundant on every rank): r -> rh directly, z -> zb0.
        //     128 pair-tasks (2 gates x 64 col-pairs), 2 rows each, 128-deep.
        if (tid < 128) {
            const bool isZ = tid >= 64;
            const int c = (tid & 63) * 2;
            const float* w = (isZ ? cz0_s : cr0_s) + c;
            float a00 = 0.f, a01 = 0.f, a10 = 0.f, a11 = 0.f;
#pragma unroll 16
            for (int kk = 0; kk < 128; kk++) {
                float2 ww = *(const float2*)&w[kk << 7];
                float x0 = h_s[kk], x1 = h_s[512 + kk];
                a00 = fmaf(x0, ww.x, a00); a01 = fmaf(x0, ww.y, a01);
                a10 = fmaf(x1, ww.x, a10); a11 = fmaf(x1, ww.y, a11);
            }
            if (!isZ) {
                float2 B0 = *(const float2*)&xrt[xr0 + c];
                float2 B1 = *(const float2*)&xrt[xr1 + c];
                rh_s[c]          = sigmoidf_(a00 + B0.x) * h_s[c];
                rh_s[c + 1]      = sigmoidf_(a01 + B0.y) * h_s[c + 1];
                rh_s[1280 + c]   = sigmoidf_(a10 + B1.x) * h_s[512 + c];
                rh_s[1280 + c+1] = sigmoidf_(a11 + B1.y) * h_s[512 + c + 1];
            } else {
                float2 B0 = *(const float2*)&xzt[xr0 + c];
                float2 B1 = *(const float2*)&xzt[xr1 + c];
                zb0[c]           = sigmoidf_(a00 + B0.x);
                zb0[c + 1]       = sigmoidf_(a01 + B0.y);
                zb0[128 + c]     = sigmoidf_(a10 + B1.x);
                zb0[128 + c + 1] = sigmoidf_(a11 + B1.y);
            }
        }
        __syncthreads();

        // ============ pass 2 (streamed blocks only; skipped on odd t) =======
        if (ns > 0) {
            int pcount[3]; int npairs = 0;
            for (int a = 0; a < ns; a++) {
                pcount[a] = (sact[a] + 1) * 16;
                npairs += pcount[a];
            }
            for (int s = tid; s < 2 * npairs; s += 512) {
                const int row = s & 1;
                int p = s >> 1;
                int i = 1;
                for (int a = 0; a < ns; a++) {
                    if (p < pcount[a]) { i = sact[a]; break; }
                    p -= pcount[a];
                }
                const int colsP = (i + 1) * 32;
                const int c2 = p * 2;
                const int j = rank * colsP + c2;
                const float* P = rp + c_RPBn[i] + row * colsP + c2;
                float s0 = 0.f, s1 = 0.f;
                const int nsg = c_SRn[i];
                for (int sg = 0; sg < nsg; sg++) {
                    s0 += P[sg * 2 * colsP];
                    s1 += P[sg * 2 * colsP + 1];
                }
                const float* hh = h_s + row * 512;
                const float v0 = sigmoidf_(s0) * hh[j];
                const float v1 = sigmoidf_(s1) * hh[j + 1];
                const int idx = c_OFF[i] + j;
                rh_s[row * 1280 + idx]     = v0;
                rh_s[row * 1280 + idx + 1] = v1;
                const uint32_t off = (uint32_t)(row * 1280 + idx) * 4u;
                st_cluster_b64(peer_rh[0] + off, v0, v1);
                st_cluster_b64(peer_rh[1] + off, v0, v1);
                st_cluster_b64(peer_rh[2] + off, v0, v1);
            }
            CLUSTER_SYNC();
        }

        // ============ pass 3: hn dots =======================================
        // (a) warp tasks: streamed blocks (rh-based)
        {
            const int nwh = (aa1 ? 4 : 0) + (aa2 ? 6 : 0) + (aa3 ? 8 : 0);
            for (int wt = wid; wt < nwh; wt += 16) {
                int k = wt;
                float A0[4] = {0,0,0,0}, A1[4] = {0,0,0,0};
                int i, seg;
                const float* base;
                if (aa1 && k < 4)      { i = 1; seg = k; base = ch1; }
                else {
                    if (aa1) k -= 4;
                    if (aa2 && k < 6)  { i = 2; seg = k; base = ch2; }
                    else { if (aa2) k -= 6; i = 3; seg = k; base = ch3; }
                }
                wdot_w8s2(base + (size_t)(seg * 64) * 128 + rank * 32, 128,
                          rh_s + c_OFF[i] + seg * 64,
                          rh_s + 1280 + c_OFF[i] + seg * 64, A0, A1, lane);
                if (lane < 8) {
                    const int c = lane * 4;
                    if (seg == 0) {
                        const int gc = (i << 7) + rank * 32 + c;
                        fold4(A0, *(const float4*)&xt[xr0 + gc]);
                        fold4(A1, *(const float4*)&xt[xr1 + gc]);
                    }
                    float* P = hp + c_ZPBn[i] + seg * 64 + c;
                    *(float4*)P        = make_float4(A0[0],A0[1],A0[2],A0[3]);
                    *(float4*)(P + 32) = make_float4(A1[0],A1[1],A1[2],A1[3]);
                }
            }
        }
        // (b) block0 hn + gate + h update (redundant, local only)
        if (tid < 64) {
            const int c = tid * 2;
            float a00 = 0.f, a01 = 0.f, a10 = 0.f, a11 = 0.f;
            const float* w = ch0_s + c;
#pragma unroll 16
            for (int kk = 0; kk < 128; kk++) {
                float2 ww = *(const float2*)&w[kk << 7];
                float x0 = rh_s[kk], x1 = rh_s[1280 + kk];
                a00 = fmaf(x0, ww.x, a00); a01 = fmaf(x0, ww.y, a01);
                a10 = fmaf(x1, ww.x, a10); a11 = fmaf(x1, ww.y, a11);
            }
            float2 B0 = *(const float2*)&xt[xr0 + c];
            float2 B1 = *(const float2*)&xt[xr1 + c];
            const float hn00 = sigmoidf_(a00 + B0.x);
            const float hn01 = sigmoidf_(a01 + B0.y);
            const float hn10 = sigmoidf_(a10 + B1.x);
            const float hn11 = sigmoidf_(a11 + B1.y);
            const float z00 = zb0[c], z01 = zb0[c + 1];
            const float z10 = zb0[128 + c], z11 = zb0[128 + c + 1];
            h_s[c]           = z00 * hn00 + (1.0f - z00) * h_s[c];
            h_s[c + 1]       = z01 * hn01 + (1.0f - z01) * h_s[c + 1];
            h_s[512 + c]     = z10 * hn10 + (1.0f - z10) * h_s[512 + c];
            h_s[512 + c + 1] = z11 * hn11 + (1.0f - z11) * h_s[512 + c + 1];
        }
        __syncthreads();

        // ============ pass 4 (streamed blocks only) =========================
        if (ns > 0) {
            const int npairs = ns * 16;
            for (int s = tid; s < 2 * npairs; s += 512) {
                const int row = s & 1;
                const int p = s >> 1;
                const int i = sact[p >> 4];
                const int c2 = (p & 15) * 2;
                const int lc = rank * 32 + c2;
                const int gc = (i << 7) + lc;
                const float* Pz = zp + c_ZPBn[i] + row * 32 + c2;
                const float* Ph = hp + c_ZPBn[i] + row * 32 + c2;
                float z0 = 0.f, z1 = 0.f, n0 = 0.f, n1 = 0.f;
                const int nsg = c_SRn[i];
                for (int sg = 0; sg < nsg; sg++) {
                    z0 += Pz[sg * 64];
                    z1 += Pz[sg * 64 + 1];
                    n0 += Ph[sg * 64];
                    n1 += Ph[sg * 64 + 1];
                }
                const float zz0 = sigmoidf_(z0), zz1 = sigmoidf_(z1);
                const float hn0 = sigmoidf_(n0), hn1 = sigmoidf_(n1);
                float* hh = h_s + row * 512;
                const float v0 = zz0 * hn0 + (1.0f - zz0) * hh[gc];
                const float v1 = zz1 * hn1 + (1.0f - zz1) * hh[gc + 1];
                hh[gc] = v0; hh[gc + 1] = v1;
                const uint32_t off = (uint32_t)(row * 512 + gc) * 4u;
                st_cluster_b64(peer_h[0] + off, v0, v1);
                st_cluster_b64(peer_h[1] + off, v0, v1);
                st_cluster_b64(peer_h[2] + off, v0, v1);
            }
            __syncthreads();
        }

        // output: own 32-col slice of each block, 2 rows (self-written h only)
        if (tid < 256) {
            const int row = tid >> 7;
            const int idx = tid & 127;
            const int i = idx >> 5, c = idx & 31;
            const int gc = i * 128 + rank * 32 + c;
            const size_t xr = row ? xr1 : xr0;
            out[xr + gc] = h_s[row * 512 + gc];
        }
        if (ns > 0) CLUSTER_SYNC();   // remote h visible before next step
    }
}

// ---------------------------------------------------------------------------
extern "C" void kernel_launch(void* const* d_in, const int* in_sizes, int n_in,
                              void* d_out, int out_size) {
    (void)in_sizes; (void)n_in; (void)out_size;
    const float* x  = (const float*)d_in[0];
    const float* W  = (const float*)d_in[1];
    const float* bb = (const float*)d_in[2];
    const float* Wr = (const float*)d_in[3];
    const float* br = (const float*)d_in[4];
    const float* Wz = (const float*)d_in[5];
    const float* bz = (const float*)d_in[6];
    const float* ch[4]; const float* cr[4]; const float* cz[4];
    for (int i = 0; i < 4; i++) {
        ch[i] = (const float*)d_in[7 + 3 * i + 0];
        cr[i] = (const float*)d_in[7 + 3 * i + 1];
        cz[i] = (const float*)d_in[7 + 3 * i + 2];
    }
    float* out = (float*)d_out;

    dim3 grid(1, 256, 12);
    gemm3_kernel<<<grid, 256>>>(x, W, bb, Wr, br, Wz, bz);

    size_t smem_bytes = 57856 * sizeof(float);   // 231,424 B (max 232,448)
    cudaFuncSetAttribute(scan_kernel,
                         cudaFuncAttributeMaxDynamicSharedMemorySize,
                         (int)smem_bytes);
    scan_kernel<<<(NBATCH / 2) * 4, 512, smem_bytes>>>(
        ch[0], cr[0], cz[0],
        ch[1], cr[1], cz[1],
        ch[2], cr[2], cz[2],
        ch[3], cr[3], cz[3],
        out);
}

// round 13
// speedup vs baseline: 1.2305x; 1.2305x over previous
#include <cuda_runtime.h>
#include <cstdint>

// ---------------------------------------------------------------------------
// ClockworkGRU  v13:
//   Phase A: clockwork-sparse projections (47% of dense GEMM).
//   Phase B: scan — 4-CTA cluster per PAIR of batch rows.
//     * block 0 computed redundantly per rank from full SMEM matrices,
//       split into 32-deep segment tasks (well-parallelized, unlike v12).
//     * odd steps: zero cluster barriers / exchanges (block0-only, local).
//     * even steps: trailing cluster barrier split (arrive at end, wait at
//       top of next even step) — odd-step work hides barrier latency.
//     * block 1 streamed via coalesced warp dots (SMEM freed for block 0).
// ---------------------------------------------------------------------------

#define GM 32768
#define GK 512
#define GN 512
#define SEQ_LEN 512
#define NBATCH 64

__device__ float g_proj[3ull * GM * GN];

__constant__ int c_OFF[4]  = {0, 128, 384, 768};
// streamed blocks 1..3 tables
__constant__ int c_SRs[4]  = {0, 2, 3, 4};      // r segs (128-deep)
__constant__ int c_RB[4]   = {0, 0, 256, 832};  // r partial bases in rp
__constant__ int c_SZs[4]  = {0, 4, 6, 8};      // z segs (64-deep)
__constant__ int c_ZB[4]   = {0, 0, 256, 640};  // z partial bases in zp
__constant__ int c_SHs[4]  = {0, 2, 3, 4};      // hn segs (128-deep)
__constant__ int c_HB[4]   = {0, 1024, 1152, 1344}; // hn bases (alias rp)

// ---------------- helpers ----------------------------------------------------
__device__ __forceinline__ unsigned long long pack2(float x, float y) {
    unsigned long long r;
    asm("mov.b64 %0, {%1, %2};" : "=l"(r) : "f"(x), "f"(y));
    return r;
}
__device__ __forceinline__ void fma2(unsigned long long& d,
                                     unsigned long long a,
                                     unsigned long long b) {
    asm("fma.rn.f32x2 %0, %1, %2, %0;" : "+l"(d) : "l"(a), "l"(b));
}
__device__ __forceinline__ float2 unpack2(unsigned long long v) {
    float2 r;
    asm("mov.b64 {%0, %1}, %2;" : "=f"(r.x), "=f"(r.y) : "l"(v));
    return r;
}
__device__ __forceinline__ float sigmoidf_(float x) {
    return 1.0f / (1.0f + __expf(-x));
}
__device__ __forceinline__ uint32_t smem_u32(const void* p) {
    return (uint32_t)__cvta_generic_to_shared(p);
}
__device__ __forceinline__ uint32_t mapa_u32(uint32_t addr, uint32_t rank) {
    uint32_t r;
    asm("mapa.shared::cluster.u32 %0, %1, %2;" : "=r"(r) : "r"(addr), "r"(rank));
    return r;
}
__device__ __forceinline__ void st_cluster_b64(uint32_t a, float x, float y) {
    unsigned long long v = pack2(x, y);
    asm volatile("st.shared::cluster.b64 [%0], %1;" :: "r"(a), "l"(v) : "memory");
}
#define CLUSTER_SYNC() do {                                           \
    asm volatile("barrier.cluster.arrive.aligned;" ::: "memory");     \
    asm volatile("barrier.cluster.wait.aligned;"   ::: "memory");     \
} while (0)
#define CLUSTER_ARRIVE() \
    asm volatile("barrier.cluster.arrive.aligned;" ::: "memory")
#define CLUSTER_WAIT() \
    asm volatile("barrier.cluster.wait.aligned;"   ::: "memory")

// ---------------------------------------------------------------------------
// Clockwork-sparse GEMM (unchanged — measured ~0.43 ms)
// ---------------------------------------------------------------------------
#define BM 128
#define BN 128
#define BKK 8

__global__ void __launch_bounds__(256) gemm3_kernel(
    const float* __restrict__ A,
    const float* __restrict__ W0, const float* __restrict__ b0,
    const float* __restrict__ W1, const float* __restrict__ b1,
    const float* __restrict__ W2, const float* __restrict__ b2)
{
    __shared__ float As[BKK][BM];
    __shared__ float Bs[BKK][BN];

    const int zi = blockIdx.z;
    const int z  = zi >> 2;
    const int cb = zi & 3;
    const int rpb_log = 9 - cb;
    const int ntiles = (NBATCH << rpb_log) >> 7;
    if ((int)blockIdx.y >= ntiles) return;

    const float* W    = (z == 0) ? W0 : (z == 1 ? W1 : W2);
    const float* bias = (z == 0) ? b0 : (z == 1 ? b1 : b2);
    float* C = g_proj + (size_t)z * GM * GN;

    const int m0 = blockIdx.y * BM;
    const int n0 = cb * 128;
    const int tid = threadIdx.x;

    const int a_row = tid >> 1;
    const int a_k   = (tid & 1) * 4;
    const int b_row = tid >> 5;
    const int b_col = (tid & 31) * 4;

    const int warp = tid >> 5;
    const int lane = tid & 31;
    const int row0 = (warp & 3) * 32 + (lane & 3) * 8;
    const int col0 = (warp >> 2) * 64 + (lane >> 2) * 8;

    const int rpb_mask = (1 << rpb_log) - 1;
    const int gA = m0 + a_row;
    const int arow_act = ((gA >> rpb_log) << 9) + ((gA & rpb_mask) << cb);

    unsigned long long acc[8][4];
#pragma unroll
    for (int i = 0; i < 8; i++)
#pragma unroll
        for (int j = 0; j < 4; j++) acc[i][j] = 0ull;

    const float* Aptr = A + (size_t)arow_act * GK + a_k;
    const float* Wptr = W + (size_t)b_row * GN + n0 + b_col;

    float4 ra = *(const float4*)Aptr;
    float4 rb = *(const float4*)Wptr;

    const int KT = GK / BKK;
    for (int kt = 0; kt < KT; kt++) {
        As[a_k + 0][a_row] = ra.x;
        As[a_k + 1][a_row] = ra.y;
        As[a_k + 2][a_row] = ra.z;
        As[a_k + 3][a_row] = ra.w;
        *(float4*)&Bs[b_row][b_col] = rb;
        __syncthreads();

        if (kt + 1 < KT) {
            ra = *(const float4*)(Aptr + (kt + 1) * BKK);
            rb = *(const float4*)(Wptr + (size_t)(kt + 1) * BKK * GN);
        }

#pragma unroll
        for (int k = 0; k < BKK; k++) {
            float4 a0 = *(const float4*)&As[k][row0];
            float4 a1 = *(const float4*)&As[k][row0 + 4];
            ulonglong2 bq0 = *(const ulonglong2*)&Bs[k][col0];
            ulonglong2 bq1 = *(const ulonglong2*)&Bs[k][col0 + 4];
            unsigned long long av[8];
            av[0] = pack2(a0.x, a0.x); av[1] = pack2(a0.y, a0.y);
            av[2] = pack2(a0.z, a0.z); av[3] = pack2(a0.w, a0.w);
            av[4] = pack2(a1.x, a1.x); av[5] = pack2(a1.y, a1.y);
            av[6] = pack2(a1.z, a1.z); av[7] = pack2(a1.w, a1.w);
#pragma unroll
            for (int i = 0; i < 8; i++) {
                fma2(acc[i][0], av[i], bq0.x);
                fma2(acc[i][1], av[i], bq0.y);
                fma2(acc[i][2], av[i], bq1.x);
                fma2(acc[i][3], av[i], bq1.y);
            }
        }
        __syncthreads();
    }

    float bb[8];
#pragma unroll
    for (int j = 0; j < 8; j++) bb[j] = bias[n0 + col0 + j];

#pragma unroll
    for (int i = 0; i < 8; i++) {
        float o[8];
#pragma unroll
        for (int jp = 0; jp < 4; jp++) {
            float2 v = unpack2(acc[i][jp]);
            o[2 * jp]     = v.x + bb[2 * jp];
            o[2 * jp + 1] = v.y + bb[2 * jp + 1];
        }
        const int g2 = m0 + row0 + i;
        const int crow = ((g2 >> rpb_log) << 9) + ((g2 & rpb_mask) << cb);
        size_t base = (size_t)crow * GN + n0 + col0;
        *(float4*)&C[base]     = make_float4(o[0], o[1], o[2], o[3]);
        *(float4*)&C[base + 4] = make_float4(o[4], o[5], o[6], o[7]);
    }
}

// ---------------------------------------------------------------------------
// warp-coalesced 2-row dots
// ---------------------------------------------------------------------------

// lanes < WIDE each own 4 consecutive cols per k-row; KD rows, 8+8 dbl-buffer.
template<int WIDE, int KD>
__device__ __forceinline__ void wdot_wide2(const float* __restrict__ Wp, int stride,
                                           const float* __restrict__ h0,
                                           const float* __restrict__ h1,
                                           float* a0, float* a1, int lane)
{
    const float* p = Wp + lane * 4;
    float4 A[8], B[8];
#pragma unroll
    for (int r = 0; r < 8; r++) A[r] = *(const float4*)(p + (size_t)r * stride);
#pragma unroll
    for (int kb = 0; kb < KD; kb += 16) {
#pragma unroll
        for (int r = 0; r < 8; r++)
            B[r] = *(const float4*)(p + (size_t)(kb + 8 + r) * stride);
#pragma unroll
        for (int r = 0; r < 8; r++) {
            float x0 = h0[kb + r], x1 = h1[kb + r];
            a0[0] = fmaf(x0, A[r].x, a0[0]); a0[1] = fmaf(x0, A[r].y, a0[1]);
            a0[2] = fmaf(x0, A[r].z, a0[2]); a0[3] = fmaf(x0, A[r].w, a0[3]);
            a1[0] = fmaf(x1, A[r].x, a1[0]); a1[1] = fmaf(x1, A[r].y, a1[1]);
            a1[2] = fmaf(x1, A[r].z, a1[2]); a1[3] = fmaf(x1, A[r].w, a1[3]);
        }
        if (kb + 16 < KD) {
#pragma unroll
            for (int r = 0; r < 8; r++)
                A[r] = *(const float4*)(p + (size_t)(kb + 16 + r) * stride);
        }
#pragma unroll
        for (int r = 0; r < 8; r++) {
            float x0 = h0[kb + 8 + r], x1 = h1[kb + 8 + r];
            a0[0] = fmaf(x0, B[r].x, a0[0]); a0[1] = fmaf(x0, B[r].y, a0[1]);
            a0[2] = fmaf(x0, B[r].z, a0[2]); a0[3] = fmaf(x0, B[r].w, a0[3]);
            a1[0] = fmaf(x1, B[r].x, a1[0]); a1[1] = fmaf(x1, B[r].y, a1[1]);
            a1[2] = fmaf(x1, B[r].z, a1[2]); a1[3] = fmaf(x1, B[r].w, a1[3]);
        }
    }
}

// one 64-row block of the 32-col window dot (no reduce)
__device__ __forceinline__ void w8s2_block(const float* __restrict__ p, int stride,
                                           const float* __restrict__ h0,
                                           const float* __restrict__ h1,
                                           int sr, float* a0, float* a1)
{
    float4 A[8], B[8];
#pragma unroll
    for (int i = 0; i < 8; i++)
        A[i] = *(const float4*)(p + (size_t)(i * 4) * stride);
#pragma unroll
    for (int i = 0; i < 8; i++)
        B[i] = *(const float4*)(p + (size_t)((i + 8) * 4) * stride);
#pragma unroll
    for (int i = 0; i < 8; i++) {
        float x0 = h0[i * 4 + sr], x1 = h1[i * 4 + sr];
        a0[0] = fmaf(x0, A[i].x, a0[0]); a0[1] = fmaf(x0, A[i].y, a0[1]);
        a0[2] = fmaf(x0, A[i].z, a0[2]); a0[3] = fmaf(x0, A[i].w, a0[3]);
        a1[0] = fmaf(x1, A[i].x, a1[0]); a1[1] = fmaf(x1, A[i].y, a1[1]);
        a1[2] = fmaf(x1, A[i].z, a1[2]); a1[3] = fmaf(x1, A[i].w, a1[3]);
    }
#pragma unroll
    for (int i = 0; i < 8; i++) {
        float x0 = h0[(i + 8) * 4 + sr], x1 = h1[(i + 8) * 4 + sr];
        a0[0] = fmaf(x0, B[i].x, a0[0]); a0[1] = fmaf(x0, B[i].y, a0[1]);
        a0[2] = fmaf(x0, B[i].z, a0[2]); a0[3] = fmaf(x0, B[i].w, a0[3]);
        a1[0] = fmaf(x1, B[i].x, a1[0]); a1[1] = fmaf(x1, B[i].y, a1[1]);
        a1[2] = fmaf(x1, B[i].z, a1[2]); a1[3] = fmaf(x1, B[i].w, a1[3]);
    }
}

// 32-col window dot over NSEG x 64 rows; shfl reduce; lanes 0-7 hold sums.
template<int NSEG>
__device__ __forceinline__ void wdot_w8s2n(const float* __restrict__ Wp, int stride,
                                           const float* __restrict__ h0,
                                           const float* __restrict__ h1,
                                           float* a0, float* a1, int lane)
{
    const int sr = lane >> 3, sc = lane & 7;
    const float* p = Wp + sr * stride + sc * 4;
#pragma unroll
    for (int s = 0; s < NSEG; s++)
        w8s2_block(p + (size_t)(s * 64) * stride, stride,
                   h0 + s * 64, h1 + s * 64, sr, a0, a1);
#pragma unroll
    for (int j = 0; j < 4; j++) {
        a0[j] += __shfl_xor_sync(0xffffffffu, a0[j], 8);
        a0[j] += __shfl_xor_sync(0xffffffffu, a0[j], 16);
        a1[j] += __shfl_xor_sync(0xffffffffu, a1[j], 8);
        a1[j] += __shfl_xor_sync(0xffffffffu, a1[j], 16);
    }
}

// block0 SMEM dot: 32-deep, 4 cols, 2 rows (full matrix stride 128 floats)
__device__ __forceinline__ void dot_b0(const float* __restrict__ w,
                                       const float* __restrict__ h0,
                                       const float* __restrict__ h1,
                                       float* a0, float* a1)
{
#pragma unroll
    for (int k = 0; k < 32; k++) {
        float4 ww = *(const float4*)&w[k << 7];
        float x0 = h0[k], x1 = h1[k];
        a0[0] = fmaf(x0, ww.x, a0[0]); a0[1] = fmaf(x0, ww.y, a0[1]);
        a0[2] = fmaf(x0, ww.z, a0[2]); a0[3] = fmaf(x0, ww.w, a0[3]);
        a1[0] = fmaf(x1, ww.x, a1[0]); a1[1] = fmaf(x1, ww.y, a1[1]);
        a1[2] = fmaf(x1, ww.z, a1[2]); a1[3] = fmaf(x1, ww.w, a1[3]);
    }
}

__device__ __forceinline__ void fold4(float* a, const float4& b) {
    a[0] += b.x; a[1] += b.y; a[2] += b.z; a[3] += b.w;
}

// ---------------------------------------------------------------------------
__global__ void __launch_bounds__(512, 1) __cluster_dims__(4, 1, 1)
scan_kernel(
    const float* __restrict__ ch0, const float* __restrict__ cr0, const float* __restrict__ cz0,
    const float* __restrict__ ch1, const float* __restrict__ cr1, const float* __restrict__ cz1,
    const float* __restrict__ ch2, const float* __restrict__ cr2, const float* __restrict__ cz2,
    const float* __restrict__ ch3, const float* __restrict__ cr3, const float* __restrict__ cz3,
    float* __restrict__ out)
{
    extern __shared__ float smem[];
    float* h_s   = smem;              // 2 x 512
    float* rh_s  = smem + 1024;       // 2 x 1280
    float* b0rp  = smem + 3584;       // 1024: [seg][row][128]
    float* b0zp  = smem + 4608;       // 1024
    float* rp    = smem + 5632;       // 1856 streamed r partials (+ hn alias)
    float* zp    = smem + 7488;       // 1152 streamed z partials
    float* cr0_s = smem + 8640;       // 128 x 128 FULL
    float* cz0_s = smem + 25024;      // 128 x 128 FULL
    float* ch0_s = smem + 41408;      // 128 x 128 FULL (end 57792 = 231,168 B)

    const int rank = blockIdx.x & 3;
    const int bp   = blockIdx.x >> 2;
    const int tid  = threadIdx.x;
    const int wid  = tid >> 5;
    const int lane = tid & 31;

    // preload FULL block-0 matrices
    {
        const float4* s1 = (const float4*)cr0; float4* d1 = (float4*)cr0_s;
        const float4* s2 = (const float4*)cz0; float4* d2 = (float4*)cz0_s;
        const float4* s3 = (const float4*)ch0; float4* d3 = (float4*)ch0_s;
        for (int i = tid; i < 4096; i += 512) {
            d1[i] = s1[i]; d2[i] = s2[i]; d3[i] = s3[i];
        }
    }
    h_s[tid] = 0.0f; h_s[512 + tid] = 0.0f;
    __syncthreads();
    CLUSTER_SYNC();

    uint32_t peer_rh[3], peer_h[3];
    {
        int p = 0;
        for (int r = 0; r < 4; r++) {
            if (r == rank) continue;
            peer_rh[p] = mapa_u32(smem_u32(rh_s), (uint32_t)r);
            peer_h[p]  = mapa_u32(smem_u32(h_s),  (uint32_t)r);
            p++;
        }
    }

    const float* xt  = g_proj;
    const float* xrt = g_proj + (size_t)GM * GN;
    const float* xzt = g_proj + 2ull * GM * GN;

    for (int t = 0; t < SEQ_LEN; t++) {
        const bool aa1 = (t & 1) == 0, aa2 = (t & 3) == 0, aa3 = (t & 7) == 0;
        int sact[3]; int ns = 0;
        if (aa1) sact[ns++] = 1;
        if (aa2) sact[ns++] = 2;
        if (aa3) sact[ns++] = 3;

        const size_t xr0 = ((size_t)(bp * 2 + 0) * SEQ_LEN + t) * GN;
        const size_t xr1 = ((size_t)(bp * 2 + 1) * SEQ_LEN + t) * GN;

        // complete the split barrier from the previous even step
        if (aa1 && t > 0) CLUSTER_WAIT();

        // ============ pass 1: r/z dots → partial slots ======================
        // (a) warp tasks: streamed blocks
        if (ns > 0) {
            const int nwt = (aa1 ? 8 : 0) + (aa2 ? 9 : 0) + (aa3 ? 12 : 0);
            for (int wt = wid; wt < nwt; wt += 16) {
                int k = wt;
                float A0[4] = {0,0,0,0}, A1[4] = {0,0,0,0};
                if (aa1) {
                    if (k < 4) {                      // b1 r: 2 grp x 2 seg128
                        const int g = k & 1, seg = k >> 1;
                        wdot_w8s2n<2>(cr1 + (size_t)(seg * 128) * 256
                                          + rank * 64 + g * 32, 256,
                                      h_s + seg * 128, h_s + 512 + seg * 128,
                                      A0, A1, lane);
                        if (lane < 8) {
                            const int c = g * 32 + lane * 4;
                            if (seg == 0) {
                                fold4(A0, *(const float4*)&xrt[xr0 + rank * 64 + c]);
                                fold4(A1, *(const float4*)&xrt[xr1 + rank * 64 + c]);
                            }
                            float* P = rp + seg * 128 + c;
                            *(float4*)P        = make_float4(A0[0],A0[1],A0[2],A0[3]);
                            *(float4*)(P + 64) = make_float4(A1[0],A1[1],A1[2],A1[3]);
                        }
                        continue;
                    }
                    k -= 4;
                    if (k < 4) {                      // b1 z: 4 seg64
                        const int seg = k;
                        wdot_w8s2n<1>(cz1 + (size_t)(seg * 64) * 128 + rank * 32,
                                      128, h_s + seg * 64, h_s + 512 + seg * 64,
                                      A0, A1, lane);
                        if (lane < 8) {
                            const int c = lane * 4;
                            if (seg == 0) {
                                fold4(A0, *(const float4*)&xzt[xr0 + 128 + rank * 32 + c]);
                                fold4(A1, *(const float4*)&xzt[xr1 + 128 + rank * 32 + c]);
                            }
                            float* P = zp + seg * 64 + c;
                            *(float4*)P        = make_float4(A0[0],A0[1],A0[2],A0[3]);
                            *(float4*)(P + 32) = make_float4(A1[0],A1[1],A1[2],A1[3]);
                        }
                        continue;
                    }
                    k -= 4;
                }
                if (aa2) {
                    if (k < 3) {                      // b2 r: 3 seg128
                        const int seg = k;
                        if (lane < 24) {
                            wdot_wide2<24, 128>(cr2 + (size_t)(seg * 128) * 384
                                                    + rank * 96, 384,
                                                h_s + seg * 128,
                                                h_s + 512 + seg * 128,
                                                A0, A1, lane);
                            const int c = lane * 4;
                            if (seg == 0) {
                                fold4(A0, *(const float4*)&xrt[xr0 + rank * 96 + c]);
                                fold4(A1, *(const float4*)&xrt[xr1 + rank * 96 + c]);
                            }
                            float* P = rp + 256 + seg * 192 + c;
                            *(float4*)P        = make_float4(A0[0],A0[1],A0[2],A0[3]);
                            *(float4*)(P + 96) = make_float4(A1[0],A1[1],A1[2],A1[3]);
                        }
                        continue;
                    }
                    k -= 3;
                    if (k < 6) {                      // b2 z: 6 seg64
                        const int seg = k;
                        wdot_w8s2n<1>(cz2 + (size_t)(seg * 64) * 128 + rank * 32,
                                      128, h_s + seg * 64, h_s + 512 + seg * 64,
                                      A0, A1, lane);
                        if (lane < 8) {
                            const int c = lane * 4;
                            if (seg == 0) {
                                fold4(A0, *(const float4*)&xzt[xr0 + 256 + rank * 32 + c]);
                                fold4(A1, *(const float4*)&xzt[xr1 + 256 + rank * 32 + c]);
                            }
                            float* P = zp + 256 + seg * 64 + c;
                            *(float4*)P        = make_float4(A0[0],A0[1],A0[2],A0[3]);
                            *(float4*)(P + 32) = make_float4(A1[0],A1[1],A1[2],A1[3]);
                        }
                        continue;
                    }
                    k -= 6;
                }
                if (k < 4) {                          // b3 r: 4 seg128
                    const int seg = k;
                    wdot_wide2<32, 128>(cr3 + (size_t)(seg * 128) * 512
                                            + rank * 128, 512,
                                        h_s + seg * 128, h_s + 512 + seg * 128,
                                        A0, A1, lane);
                    const int c = lane * 4;
                    if (seg == 0) {
                        fold4(A0, *(const float4*)&xrt[xr0 + rank * 128 + c]);
                        fold4(A1, *(const float4*)&xrt[xr1 + rank * 128 + c]);
                    }
                    float* P = rp + 832 + seg * 256 + c;
                    *(float4*)P         = make_float4(A0[0],A0[1],A0[2],A0[3]);
                    *(float4*)(P + 128) = make_float4(A1[0],A1[1],A1[2],A1[3]);
                } else {                              // b3 z: 8 seg64
                    const int seg = k - 4;
                    wdot_w8s2n<1>(cz3 + (size_t)(seg * 64) * 128 + rank * 32,
                                  128, h_s + seg * 64, h_s + 512 + seg * 64,
                                  A0, A1, lane);
                    if (lane < 8) {
                        const int c = lane * 4;
                        if (seg == 0) {
                            fold4(A0, *(const float4*)&xzt[xr0 + 384 + rank * 32 + c]);
                            fold4(A1, *(const float4*)&xzt[xr1 + 384 + rank * 32 + c]);
                        }
                        float* P = zp + 640 + seg * 64 + c;
                        *(float4*)P        = make_float4(A0[0],A0[1],A0[2],A0[3]);
                        *(float4*)(P + 32) = make_float4(A1[0],A1[1],A1[2],A1[3]);
                    }
                }
            }
        }
        // (b) block0 r/z tasks (redundant, SMEM): 256 tasks on tid>=256
        if (tid >= 256) {
            const int tk = tid - 256;
            const bool isZ = tk >= 128;
            const int r2 = tk & 127;
            const int seg = r2 >> 5, q = r2 & 31, c = q * 4;
            float A0[4] = {0,0,0,0}, A1[4] = {0,0,0,0};
            const float* w = (isZ ? cz0_s : cr0_s) + (seg * 32) * 128 + c;
            dot_b0(w, h_s + seg * 32, h_s + 512 + seg * 32, A0, A1);
            if (seg == 0) {
                const float* xb = isZ ? xzt : xrt;
                fold4(A0, *(const float4*)&xb[xr0 + c]);
                fold4(A1, *(const float4*)&xb[xr1 + c]);
            }
            float* P = (isZ ? b0zp : b0rp) + seg * 256 + c;
            *(float4*)P         = make_float4(A0[0], A0[1], A0[2], A0[3]);
            *(float4*)(P + 128) = make_float4(A1[0], A1[1], A1[2], A1[3]);
        }
        __syncthreads();

        // ============ pass 2: reduce r → rh =================================
        {
            int pcount[3]; int nst = 0;
            for (int a = 0; a < ns; a++) {
                pcount[a] = (sact[a] + 1) * 16;
                nst += pcount[a];
            }
            const int total2 = 128 + 2 * nst;   // 128 b0 units + streamed
            for (int s = tid; s < total2; s += 512) {
                if (s < 128) {                  // block0 (local only)
                    const int row = s & 1;
                    const int c = (s >> 1) * 2;
                    const float* P = b0rp + row * 128 + c;
                    float s0 = 0.f, s1 = 0.f;
#pragma unroll
                    for (int sg = 0; sg < 4; sg++) {
                        s0 += P[sg * 256];
                        s1 += P[sg * 256 + 1];
                    }
                    const float* hh = h_s + row * 512;
                    rh_s[row * 1280 + c]     = sigmoidf_(s0) * hh[c];
                    rh_s[row * 1280 + c + 1] = sigmoidf_(s1) * hh[c + 1];
                } else {                        // streamed blocks + exchange
                    const int s2 = s - 128;
                    const int row = s2 & 1;
                    int p = s2 >> 1;
                    int i = 1;
                    for (int a = 0; a < ns; a++) {
                        if (p < pcount[a]) { i = sact[a]; break; }
                        p -= pcount[a];
                    }
                    const int colsP = (i + 1) * 32;
                    const int c2 = p * 2;
                    const int j = rank * colsP + c2;
                    const float* P = rp + c_RB[i] + row * colsP + c2;
                    float s0 = 0.f, s1 = 0.f;
                    const int nsg = c_SRs[i];
                    for (int sg = 0; sg < nsg; sg++) {
                        s0 += P[sg * 2 * colsP];
                        s1 += P[sg * 2 * colsP + 1];
                    }
                    const float* hh = h_s + row * 512;
                    const float v0 = sigmoidf_(s0) * hh[j];
                    const float v1 = sigmoidf_(s1) * hh[j + 1];
                    const int idx = c_OFF[i] + j;
                    rh_s[row * 1280 + idx]     = v0;
                    rh_s[row * 1280 + idx + 1] = v1;
                    const uint32_t off = (uint32_t)(row * 1280 + idx) * 4u;
                    st_cluster_b64(peer_rh[0] + off, v0, v1);
                    st_cluster_b64(peer_rh[1] + off, v0, v1);
                    st_cluster_b64(peer_rh[2] + off, v0, v1);
                }
            }
        }
        if (ns > 0) CLUSTER_SYNC();
        else        __syncthreads();

        // ============ pass 3: hn dots =======================================
        // (a) warp tasks: streamed blocks (128-deep)
        if (ns > 0) {
            const int nwh = (aa1 ? 2 : 0) + (aa2 ? 3 : 0) + (aa3 ? 4 : 0);
            for (int wt = wid; wt < nwh; wt += 16) {
                int k = wt;
                float A0[4] = {0,0,0,0}, A1[4] = {0,0,0,0};
                int i, seg;
                const float* base;
                if (aa1 && k < 2)      { i = 1; seg = k; base = ch1; }
                else {
                    if (aa1) k -= 2;
                    if (aa2 && k < 3)  { i = 2; seg = k; base = ch2; }
                    else { if (aa2) k -= 3; i = 3; seg = k; base = ch3; }
                }
                wdot_w8s2n<2>(base + (size_t)(seg * 128) * 128 + rank * 32, 128,
                              rh_s + c_OFF[i] + seg * 128,
                              rh_s + 1280 + c_OFF[i] + seg * 128, A0, A1, lane);
                if (lane < 8) {
                    const int c = lane * 4;
                    if (seg == 0) {
                        const int gc = (i << 7) + rank * 32 + c;
                        fold4(A0, *(const float4*)&xt[xr0 + gc]);
                        fold4(A1, *(const float4*)&xt[xr1 + gc]);
                    }
                    float* P = rp + c_HB[i] + seg * 64 + c;
                    *(float4*)P        = make_float4(A0[0],A0[1],A0[2],A0[3]);
                    *(float4*)(P + 32) = make_float4(A1[0],A1[1],A1[2],A1[3]);
                }
            }
        }
        // (b) block0 hn tasks (redundant, SMEM): 128 tasks on tid>=384
        if (tid >= 384) {
            const int tk = tid - 384;
            const int seg = tk >> 5, q = tk & 31, c = q * 4;
            float A0[4] = {0,0,0,0}, A1[4] = {0,0,0,0};
            dot_b0(ch0_s + (seg * 32) * 128 + c,
                   rh_s + seg * 32, rh_s + 1280 + seg * 32, A0, A1);
            if (seg == 0) {
                fold4(A0, *(const float4*)&xt[xr0 + c]);
                fold4(A1, *(const float4*)&xt[xr1 + c]);
            }
            float* P = rp + seg * 256 + c;   // b0h aliases rp[0:1024)
            *(float4*)P         = make_float4(A0[0], A0[1], A0[2], A0[3]);
            *(float4*)(P + 128) = make_float4(A1[0], A1[1], A1[2], A1[3]);
        }
        __syncthreads();

        // ============ pass 4: reduce z/hn, gate, update h ===================
        {
            const int total4 = 128 + 2 * (ns * 16);
            for (int s = tid; s < total4; s += 512) {
                if (s < 128) {                  // block0 (local only)
                    const int row = s & 1;
                    const int c = (s >> 1) * 2;
                    const float* Pz = b0zp + row * 128 + c;
                    const float* Ph = rp + row * 128 + c;
                    float z0 = 0.f, z1 = 0.f, n0 = 0.f, n1 = 0.f;
#pragma unroll
                    for (int sg = 0; sg < 4; sg++) {
                        z0 += Pz[sg * 256]; z1 += Pz[sg * 256 + 1];
                        n0 += Ph[sg * 256]; n1 += Ph[sg * 256 + 1];
                    }
                    const float zz0 = sigmoidf_(z0), zz1 = sigmoidf_(z1);
                    const float hn0 = sigmoidf_(n0), hn1 = sigmoidf_(n1);
                    float* hh = h_s + row * 512;
                    hh[c]     = zz0 * hn0 + (1.0f - zz0) * hh[c];
                    hh[c + 1] = zz1 * hn1 + (1.0f - zz1) * hh[c + 1];
                } else {                        // streamed + exchange
                    const int s2 = s - 128;
                    const int row = s2 & 1;
                    const int p = s2 >> 1;
                    const int i = sact[p >> 4];
                    const int c2 = (p & 15) * 2;
                    const int lc = rank * 32 + c2;
                    const int gc = (i << 7) + lc;
                    const float* Pz = zp + c_ZB[i] + row * 32 + c2;
                    const float* Ph = rp + c_HB[i] + row * 32 + c2;
                    float z0 = 0.f, z1 = 0.f, n0 = 0.f, n1 = 0.f;
                    const int nz = c_SZs[i];
                    for (int sg = 0; sg < nz; sg++) {
                        z0 += Pz[sg * 64]; z1 += Pz[sg * 64 + 1];
                    }
                    const int nh = c_SHs[i];
                    for (int sg = 0; sg < nh; sg++) {
                        n0 += Ph[sg * 64]; n1 += Ph[sg * 64 + 1];
                    }
                    const float zz0 = sigmoidf_(z0), zz1 = sigmoidf_(z1);
                    const float hn0 = sigmoidf_(n0), hn1 = sigmoidf_(n1);
                    float* hh = h_s + row * 512;
                    const float v0 = zz0 * hn0 + (1.0f - zz0) * hh[gc];
                    const float v1 = zz1 * hn1 + (1.0f - zz1) * hh[gc + 1];
                    hh[gc] = v0; hh[gc + 1] = v1;
                    const uint32_t off = (uint32_t)(row * 512 + gc) * 4u;
                    st_cluster_b64(peer_h[0] + off, v0, v1);
                    st_cluster_b64(peer_h[1] + off, v0, v1);
                    st_cluster_b64(peer_h[2] + off, v0, v1);
                }
            }
        }
        __syncthreads();

        // ============ output =================================================
        if (ns > 0) {
            // row t: own 32-col slice of all 4 blocks, both batch rows
            if (tid < 256) {
                const int row = tid >> 7;
                const int idx = tid & 127;
                const int i = idx >> 5, c = idx & 31;
                const int gc = i * 128 + rank * 32 + c;
                const size_t xr = row ? xr1 : xr0;
                out[xr + gc] = h_s[row * 512 + gc];
            } else if (tid < 448) {
                // pre-write row t+1 for blocks 1-3 (unchanged at odd t+1)
                const int s = tid - 256;
                const int row = s / 96;
                const int idx = s % 96;
                const int i = 1 + (idx >> 5), c = idx & 31;
                const int gc = i * 128 + rank * 32 + c;
                const size_t xr = (row ? xr1 : xr0) + GN;   // time t+1
                out[xr + gc] = h_s[row * 512 + gc];
            }
            CLUSTER_ARRIVE();   // completed by WAIT at the next even step
        } else {
            // odd step: only block-0 cols changed
            if (tid < 64) {
                const int row = tid >> 5, c = tid & 31;
                const int gc = rank * 32 + c;
                const size_t xr = row ? xr1 : xr0;
                out[xr + gc] = h_s[row * 512 + gc];
            }
        }
    }
}

// ---------------------------------------------------------------------------
extern "C" void kernel_launch(void* const* d_in, const int* in_sizes, int n_in,
                              void* d_out, int out_size) {
    (void)in_sizes; (void)n_in; (void)out_size;
    const float* x  = (const float*)d_in[0];
    const float* W  = (const float*)d_in[1];
    const float* bb = (const float*)d_in[2];
    const float* Wr = (const float*)d_in[3];
    const float* br = (const float*)d_in[4];
    const float* Wz = (const float*)d_in[5];
    const float* bz = (const float*)d_in[6];
    const float* ch[4]; const float* cr[4]; const float* cz[4];
    for (int i = 0; i < 4; i++) {
        ch[i] = (const float*)d_in[7 + 3 * i + 0];
        cr[i] = (const float*)d_in[7 + 3 * i + 1];
        cz[i] = (const float*)d_in[7 + 3 * i + 2];
    }
    float* out = (float*)d_out;

    dim3 grid(1, 256, 12);
    gemm3_kernel<<<grid, 256>>>(x, W, bb, Wr, br, Wz, bz);

    size_t smem_bytes = 57792 * sizeof(float);   // 231,168 B
    cudaFuncSetAttribute(scan_kernel,
                         cudaFuncAttributeMaxDynamicSharedMemorySize,
                         (int)smem_bytes);
    scan_kernel<<<(NBATCH / 2) * 4, 512, smem_bytes>>>(
        ch[0], cr[0], cz[0],
        ch[1], cr[1], cz[1],
        ch[2], cr[2], cz[2],
        ch[3], cr[3], cz[3],
        out);
}